// round 17
// baseline (speedup 1.0000x reference)
#include <cuda_runtime.h>
#include <cuda_fp16.h>
#include <cstdint>

#define THREADS 256
#define TILE_M  64
#define D_DIM   128
#define K_RBF   64

// strides in fp16 elements
#define W_STR   136      // 128 + 8 pad
#define A1_STR  72       // 64 + 8 pad
#define A2_STR  136
#define FB_STR  132      // halves per fbuf row (8B-mult)

// ---------------- smem layout (bytes) ----------------
#define OFF_W1H  0
#define OFF_W2H  (OFF_W1H + K_RBF * W_STR * 2)        // 17408
#define OFF_A1   (OFF_W2H + D_DIM * W_STR * 2)        // 52224
#define OFF_A2   (OFF_A1 + TILE_M * A1_STR * 2)       // 61440
#define OFF_FBUF OFF_A2                                // fp16 fbuf (16896 <= 17408)
#define OFF_B1S  (OFF_A2 + TILE_M * A2_STR * 2)       // 78848
#define OFF_B2S  (OFF_B1S + 512)
#define OFF_CEN  (OFF_B2S + 512)
#define OFF_GAM  (OFF_CEN + 256)
#define OFF_EMS  (OFF_GAM + 256)                       // int2[2][64]
#define SMEM_TOTAL (OFF_EMS + 1024)                    // 81408 -> 2 CTAs/SM

typedef unsigned long long u64;

// ---------------- PTX helpers ----------------
static __device__ __forceinline__ uint32_t smem_u32(const void* p) {
    uint32_t a;
    asm("{ .reg .u64 t; cvta.to.shared.u64 t, %1; cvt.u32.u64 %0, t; }" : "=r"(a) : "l"(p));
    return a;
}

#define BAR_GRP(id) asm volatile("bar.sync %0, %1;" :: "r"(id), "r"(128) : "memory")

#define LDSM_X4(r, addr)                                                     \
    asm volatile("ldmatrix.sync.aligned.m8n8.x4.shared.b16 {%0,%1,%2,%3}, [%4];" \
        : "=r"((r)[0]), "=r"((r)[1]), "=r"((r)[2]), "=r"((r)[3]) : "r"(addr))

#define LDSM_X4T(r, addr)                                                    \
    asm volatile("ldmatrix.sync.aligned.m8n8.x4.trans.shared.b16 {%0,%1,%2,%3}, [%4];" \
        : "=r"((r)[0]), "=r"((r)[1]), "=r"((r)[2]), "=r"((r)[3]) : "r"(addr))

#define MMA_F16(c, a, b0, b1)                                                \
    asm("mma.sync.aligned.m16n8k16.row.col.f32.f16.f16.f32 "                \
        "{%0,%1,%2,%3}, {%4,%5,%6,%7}, {%8,%9}, {%0,%1,%2,%3};"             \
        : "+f"((c)[0]), "+f"((c)[1]), "+f"((c)[2]), "+f"((c)[3])            \
        : "r"((a)[0]), "r"((a)[1]), "r"((a)[2]), "r"((a)[3]),               \
          "r"(b0), "r"(b1))

#define REDG_V4F32(addr, x, y, z, ww)                                        \
    asm volatile("red.global.add.v4.f32 [%0], {%1, %2, %3, %4};"            \
        :: "l"(addr), "f"(x), "f"(y), "f"(z), "f"(ww) : "memory")

// packed f32x2
static __device__ __forceinline__ u64 pk2(float lo, float hi) {
    u64 r; asm("mov.b64 %0, {%1, %2};" : "=l"(r) : "f"(lo), "f"(hi)); return r;
}
#define FMA2(d, a, b, c) asm("fma.rn.f32x2 %0, %1, %2, %3;" : "=l"(d) : "l"(a), "l"(b), "l"(c))
#define ADD2(d, a, b)    asm("add.rn.f32x2 %0, %1, %2;"     : "=l"(d) : "l"(a), "l"(b))

// shifted-softplus poly constants: log(1.5+t) Taylor (u = t/1.5), c0 folds -ln2
struct SspC { u64 nh, c6, c5, c4, c3, c2, c1, c0; };

// ssp on a pair: 2 MUFU (ex2) + packed degree-6 log1p poly
static __device__ __forceinline__ float2 ssp2(float x0, float x1, const SspC& C) {
    const float e0 = __expf(-fabsf(x0));
    const float e1 = __expf(-fabsf(x1));
    u64 t; ADD2(t, pk2(e0, e1), C.nh);         // t = s - 0.5
    u64 p = C.c6;
    FMA2(p, p, t, C.c5);
    FMA2(p, p, t, C.c4);
    FMA2(p, p, t, C.c3);
    FMA2(p, p, t, C.c2);
    FMA2(p, p, t, C.c1);
    FMA2(p, p, t, C.c0);                        // log1p(s) - ln2
    u64 r; ADD2(r, p, pk2(fmaxf(x0, 0.f), fmaxf(x1, 0.f)));
    float r0, r1;
    asm("mov.b64 {%0, %1}, %2;" : "=f"(r0), "=f"(r1) : "l"(r));
    return make_float2(r0, r1);
}

static __device__ __forceinline__ uint32_t pack_f16x2(float f0, float f1) {
    uint32_t r;
    asm("cvt.rn.f16x2.f32 %0, %1, %2;" : "=r"(r) : "f"(f1), "f"(f0));
    return r;
}

__global__ void zero_out_kernel(float* __restrict__ out, size_t n) {
    size_t i = (size_t)blockIdx.x * blockDim.x + threadIdx.x;
    size_t stride = (size_t)gridDim.x * blockDim.x;
    for (; i < n; i += stride) out[i] = 0.f;
}

extern __shared__ char smem[];

__global__ void __launch_bounds__(THREADS, 2)
cfconv_mma_kernel(const float* __restrict__ AF,     // [B,N,D]
                  const float* __restrict__ dist,   // [B,E]
                  const int*   __restrict__ idx_j,  // [E]
                  const int*   __restrict__ seg_i,  // [E] sorted
                  const float* __restrict__ W1,     // [K,D]
                  const float* __restrict__ b1,
                  const float* __restrict__ W2,     // [D,D]
                  const float* __restrict__ b2,
                  const float* __restrict__ centers,
                  const float* __restrict__ gamma,
                  float* __restrict__ out,          // [B,N,D]
                  int B, int N, int E)
{
    const uint32_t sb = smem_u32(smem);
    const int tid  = threadIdx.x;
    const int w    = tid >> 5;
    const int lane = tid & 31;

    float*  b1s = (float*)(smem + OFF_B1S);
    float*  b2s = (float*)(smem + OFF_B2S);
    float*  cen = (float*)(smem + OFF_CEN);
    float*  gam = (float*)(smem + OFF_GAM);
    __half* fb  = (__half*)(smem + OFF_FBUF);

    SspC C;
    C.nh = pk2(-0.5f, -0.5f);
    C.c6 = pk2(-0.014631915f, -0.014631915f);
    C.c5 = pk2( 0.026337449f,  0.026337449f);
    C.c4 = pk2(-0.049382716f, -0.049382716f);
    C.c3 = pk2( 0.098765432f,  0.098765432f);
    C.c2 = pk2(-0.222222222f, -0.222222222f);
    C.c1 = pk2( 0.666666667f,  0.666666667f);
    C.c0 = pk2(-0.287682072f, -0.287682072f);   // ln(1.5) - ln(2)

    // ---- weight prep: fp16, padded row-major [K][D] ----
    for (int i = tid; i < K_RBF * D_DIM; i += THREADS) {
        const int k = i >> 7, d = i & 127;
        *(__half*)(smem + OFF_W1H + (k * W_STR + d) * 2) = __float2half_rn(W1[i]);
    }
    for (int i = tid; i < D_DIM * D_DIM; i += THREADS) {
        const int k = i >> 7, d = i & 127;
        *(__half*)(smem + OFF_W2H + (k * W_STR + d) * 2) = __float2half_rn(W2[i]);
    }
    if (tid < D_DIM) { b1s[tid] = b1[tid]; b2s[tid] = b2[tid]; }
    else if (tid >= 128 && tid < 128 + K_RBF) {
        const int k = tid - 128; cen[k] = centers[k]; gam[k] = gamma[k];
    }
    __syncthreads();

    // warp tiling: 2x4 warp grid, each warp owns 32 edges x 32 cols
    const int wm = w & 1;
    const int wn = w >> 1;
    const int r0 = wm * 32;
    const int d0 = wn * 32;
    const int arow = lane & 15;
    const int acol = (lane >> 4) * 8;
    const int gr   = lane >> 2;
    const int cc   = (lane & 3) * 2;

    const int tiles_pb = (E + TILE_M - 1) / TILE_M;
    const int total    = B * tiles_pb;

    auto rbf_phase = [&](int gidx, int par) {
        const int bb_ = gidx / tiles_pb;
        const int e0_ = (gidx - bb_ * tiles_pb) * TILE_M;
        const int ne_ = min(TILE_M, E - e0_);
        const float* db_ = dist + (size_t)bb_ * E;
        const int el = r0 + lane;
        const int kb = wn * 16;
        const int eg = e0_ + min(el, ne_ - 1);
        const float dv = __ldg(&db_[eg]);
        float c4[16], g4[16];
        #pragma unroll
        for (int i = 0; i < 4; i++) {
            *(float4*)&c4[i * 4] = *(const float4*)&cen[kb + i * 4];
            *(float4*)&g4[i * 4] = *(const float4*)&gam[kb + i * 4];
        }
        #pragma unroll
        for (int kk = 0; kk < 16; kk += 2) {
            const float t0 = dv - c4[kk];
            const float t1 = dv - c4[kk + 1];
            const float v0 = __expf(-g4[kk]     * t0 * t0);
            const float v1 = __expf(-g4[kk + 1] * t1 * t1);
            const uint32_t byt = (uint32_t)(el * A1_STR + kb + kk) * 2;
            *(uint32_t*)(smem + OFF_A1 + byt) = pack_f16x2(v0, v1);
        }
        if (tid < TILE_M) {
            const int e = e0_ + min(tid, ne_ - 1);
            ((int2*)(smem + OFF_EMS))[par * TILE_M + tid] =
                make_int2(__ldg(&idx_j[e]), __ldg(&seg_i[e]));
        }
    };

    int parity = 0;
    const int g0 = blockIdx.x;
    if (g0 < total) rbf_phase(g0, parity);
    __syncthreads();

    for (int g = g0; g < total; g += gridDim.x) {
        const int b  = g / tiles_pb;
        const int e0 = (g - b * tiles_pb) * TILE_M;
        const int ne = min(TILE_M, E - e0);

        float c[2][4][4];
        #pragma unroll
        for (int mt = 0; mt < 2; mt++)
            #pragma unroll
            for (int nt = 0; nt < 4; nt++)
                { c[mt][nt][0]=0.f; c[mt][nt][1]=0.f; c[mt][nt][2]=0.f; c[mt][nt][3]=0.f; }

        // -------- GEMM1: [32x64] x W1[:,d0:d0+32] --------
        #pragma unroll
        for (int k = 0; k < 4; k++) {
            uint32_t a[2][4];
            #pragma unroll
            for (int mt = 0; mt < 2; mt++) {
                const uint32_t ab = (uint32_t)((r0 + mt*16 + arow) * A1_STR + k*16 + acol) * 2;
                LDSM_X4(a[mt], sb + OFF_A1 + ab);
            }
            const uint32_t brow = (uint32_t)((k*16 + arow) * W_STR + d0 + acol) * 2;
            #pragma unroll
            for (int p = 0; p < 2; p++) {
                uint32_t bh[4];
                LDSM_X4T(bh, sb + OFF_W1H + brow + (uint32_t)(p * 16) * 2);
                #pragma unroll
                for (int q = 0; q < 2; q++)
                    #pragma unroll
                    for (int mt = 0; mt < 2; mt++)
                        MMA_F16(c[mt][2*p+q], a[mt], bh[2*q], bh[2*q+1]);
            }
        }

        // -------- Epilogue 1: +b1, ssp2, fp16 -> A2 --------
        #pragma unroll
        for (int mt = 0; mt < 2; mt++) {
            #pragma unroll
            for (int nt = 0; nt < 4; nt++) {
                const int col = d0 + nt*8 + cc;
                const float2 bb = *(const float2*)&b1s[col];
                const float2 fa = ssp2(c[mt][nt][0] + bb.x, c[mt][nt][1] + bb.y, C);
                const float2 fc = ssp2(c[mt][nt][2] + bb.x, c[mt][nt][3] + bb.y, C);
                const uint32_t r0b = (uint32_t)((r0 + mt*16 + gr)     * A2_STR + col) * 2;
                const uint32_t r1b = (uint32_t)((r0 + mt*16 + gr + 8) * A2_STR + col) * 2;
                *(uint32_t*)(smem + OFF_A2 + r0b) = pack_f16x2(fa.x, fa.y);
                *(uint32_t*)(smem + OFF_A2 + r1b) = pack_f16x2(fc.x, fc.y);
                c[mt][nt][0]=0.f; c[mt][nt][1]=0.f; c[mt][nt][2]=0.f; c[mt][nt][3]=0.f;
            }
        }
        BAR_GRP(1 + wm);

        // -------- GEMM2: [32x128] x W2[:,d0:d0+32] --------
        #pragma unroll
        for (int k = 0; k < 8; k++) {
            uint32_t a[2][4];
            #pragma unroll
            for (int mt = 0; mt < 2; mt++) {
                const uint32_t ab = (uint32_t)((r0 + mt*16 + arow) * A2_STR + k*16 + acol) * 2;
                LDSM_X4(a[mt], sb + OFF_A2 + ab);
            }
            const uint32_t brow = (uint32_t)((k*16 + arow) * W_STR + d0 + acol) * 2;
            #pragma unroll
            for (int p = 0; p < 2; p++) {
                uint32_t bh[4];
                LDSM_X4T(bh, sb + OFF_W2H + brow + (uint32_t)(p * 16) * 2);
                #pragma unroll
                for (int q = 0; q < 2; q++)
                    #pragma unroll
                    for (int mt = 0; mt < 2; mt++)
                        MMA_F16(c[mt][2*p+q], a[mt], bh[2*q], bh[2*q+1]);
            }
        }
        __syncthreads();   // ALL A2 reads done before fbuf (A2 overlay) writes

        // -------- Epilogue 2: +b2, ssp2 -> fbuf (fp16) --------
        #pragma unroll
        for (int mt = 0; mt < 2; mt++) {
            #pragma unroll
            for (int nt = 0; nt < 4; nt++) {
                const int col = d0 + nt*8 + cc;
                const float2 bb = *(const float2*)&b2s[col];
                const float2 fa = ssp2(c[mt][nt][0] + bb.x, c[mt][nt][1] + bb.y, C);
                const float2 fc = ssp2(c[mt][nt][2] + bb.x, c[mt][nt][3] + bb.y, C);
                *(uint32_t*)&fb[(r0 + mt*16 + gr)     * FB_STR + col] = pack_f16x2(fa.x, fa.y);
                *(uint32_t*)&fb[(r0 + mt*16 + gr + 8) * FB_STR + col] = pack_f16x2(fc.x, fc.y);
            }
        }
        __syncthreads();

        // -------- Overlap: RBF(next tile) -> A1  ||  gather(g) from fbuf --------
        const int gnext = g + gridDim.x;
        if (gnext < total) rbf_phase(gnext, parity ^ 1);

        {
            const int2* ems = (const int2*)(smem + OFF_EMS) + parity * TILE_M;
            const int ch = (tid & 31) * 4;
            const int sp = tid >> 5;
            const float* AFp = AF + (size_t)b * N * D_DIM;
            float*       Op  = out + (size_t)b * N * D_DIM;
            int cur = -1; float4 acc = make_float4(0.f, 0.f, 0.f, 0.f);
            const int e_beg = sp * 8;

            if (ne == TILE_M) {
                float4 m[8]; int sr[8];
                #pragma unroll
                for (int e = 0; e < 8; e++) {
                    const int2 js = ems[e_beg + e];
                    sr[e] = js.y;
                    const float4 af = *(const float4*)&AFp[(size_t)js.x * D_DIM + ch];
                    const __half2* fp = (const __half2*)&fb[(e_beg + e) * FB_STR + ch];
                    const float2 fl = __half22float2(fp[0]);
                    const float2 fh = __half22float2(fp[1]);
                    m[e] = make_float4(af.x * fl.x, af.y * fl.y, af.z * fh.x, af.w * fh.y);
                }
                #pragma unroll
                for (int e = 0; e < 8; e++) {
                    if (sr[e] != cur) {
                        if (cur >= 0) REDG_V4F32(&Op[(size_t)cur * D_DIM + ch],
                                                 acc.x, acc.y, acc.z, acc.w);
                        cur = sr[e]; acc = m[e];
                    } else {
                        acc.x += m[e].x; acc.y += m[e].y;
                        acc.z += m[e].z; acc.w += m[e].w;
                    }
                }
            } else {
                const int e_end = min(e_beg + 8, ne);
                for (int e = e_beg; e < e_end; e++) {
                    const int2 js = ems[e];
                    const float4 af = *(const float4*)&AFp[(size_t)js.x * D_DIM + ch];
                    const __half2* fp = (const __half2*)&fb[e * FB_STR + ch];
                    const float2 fl = __half22float2(fp[0]);
                    const float2 fh = __half22float2(fp[1]);
                    const float4 m = make_float4(af.x * fl.x, af.y * fl.y,
                                                 af.z * fh.x, af.w * fh.y);
                    if (js.y != cur) {
                        if (cur >= 0) REDG_V4F32(&Op[(size_t)cur * D_DIM + ch],
                                                 acc.x, acc.y, acc.z, acc.w);
                        cur = js.y; acc = m;
                    } else {
                        acc.x += m.x; acc.y += m.y; acc.z += m.z; acc.w += m.w;
                    }
                }
            }
            if (cur >= 0) REDG_V4F32(&Op[(size_t)cur * D_DIM + ch],
                                     acc.x, acc.y, acc.z, acc.w);
        }
        parity ^= 1;
        __syncthreads();
    }
}

extern "C" void kernel_launch(void* const* d_in, const int* in_sizes, int n_in,
                              void* d_out, int out_size) {
    // order: atom_features, distances, idx_j, seg_i, centers, gamma, W1, b1, W2, b2
    const float* AF      = (const float*)d_in[0];
    const float* dist    = (const float*)d_in[1];
    const int*   idx_j   = (const int*)  d_in[2];
    const int*   seg_i   = (const int*)  d_in[3];
    const float* centers = (const float*)d_in[4];
    const float* gamma   = (const float*)d_in[5];
    const float* W1      = (const float*)d_in[6];
    const float* b1      = (const float*)d_in[7];
    const float* W2      = (const float*)d_in[8];
    const float* b2      = (const float*)d_in[9];
    float* out = (float*)d_out;

    const int E = in_sizes[2];
    const int B = in_sizes[1] / E;
    const int D = in_sizes[7];              // 128
    const int N = in_sizes[0] / (B * D);

    zero_out_kernel<<<2048, 256>>>(out, (size_t)out_size);

    cudaFuncSetAttribute(cfconv_mma_kernel,
                         cudaFuncAttributeMaxDynamicSharedMemorySize, SMEM_TOTAL);
    cfconv_mma_kernel<<<296, THREADS, SMEM_TOTAL>>>(
        AF, dist, idx_j, seg_i, W1, b1, W2, b2, centers, gamma, out, B, N, E);
}